// round 17
// baseline (speedup 1.0000x reference)
#include <cuda_runtime.h>
#include <math.h>

#define NN 132
#define MM 264
#define NPIX (NN*NN)
#define NIMG 256
#define NCH  64
#define PIF 3.14159265358979323846f

typedef unsigned long long u64;

__device__ __forceinline__ u64 pk(float x, float y) {
    u64 r; asm("mov.b64 %0, {%1,%2};" : "=l"(r) : "f"(x), "f"(y)); return r;
}
__device__ __forceinline__ float2 upk(u64 v) {
    float2 r; asm("mov.b64 {%0,%1}, %2;" : "=f"(r.x), "=f"(r.y) : "l"(v)); return r;
}
#define FMA2(acc, a, b) asm("fma.rn.f32x2 %0, %1, %2, %0;" : "+l"(acc) : "l"(a), "l"(b))

// ---------------- static scratch ----------------
__device__ ulonglong2 g_CSd[68*68];        // {pk(c,c), pk(s,s)}; zero at k==67||n==67
__device__ ulonglong2 g_Bd3[68*132];       // [k2][m2]: {pk(c,c), pk(-s,s)}; zero row k2==67
__device__ u64        g_G4[68*68];         // [m1][k1]: pk(g*c, -g*s); 0 at k1==67
__device__ u64        g_xfP[NIMG*4*68*34]; // folded x, j-pair packed
__device__ float      g_z[NIMG*NPIX];
__device__ float2     g_R[NCH*NPIX];
__device__ float2     g_E1[MM*3];
__device__ float2     g_U1[MM];
__device__ float2     g_WB[NCH*MM*3];

extern __shared__ char s_dyn[];

// ---------------- fused constant tables ----------------
__global__ void k_tables() {
    int idx = blockIdx.x * blockDim.x + threadIdx.x;
    if (idx < 4624) {
        int k = idx / 68, n = idx % 68;
        ulonglong2 v;
        if (k == 67 || n == 67) { v.x = 0ULL; v.y = 0ULL; }
        else {
            int t = (k * n) % NN;
            float ang = (2.0f * PIF / NN) * (float)t;
            float s, c; sincosf(ang, &s, &c);
            v.x = pk(c, c); v.y = pk(s, s);
        }
        g_CSd[idx] = v;
    } else if (idx < 13600) {
        int i = idx - 4624;
        int k2 = i / 132, m2 = i % 132;
        ulonglong2 v;
        if (k2 == 67) { v.x = 0ULL; v.y = 0ULL; }
        else {
            int t = (k2 * m2) % NN;
            float ang = (2.0f * PIF / NN) * (float)t;
            float s, c; sincosf(ang, &s, &c);
            v.x = pk(c, c); v.y = pk(-s, s);
        }
        g_Bd3[i] = v;
    } else if (idx < 18224) {
        int i = idx - 13600;
        int m1 = i / 68, k1 = i % 68;
        if (k1 == 67) { g_G4[i] = 0ULL; return; }
        float g = (k1 == 0 || k1 == 66) ? 1.0f : 2.0f;
        int t = (k1 * m1) % NN;
        float ang = (2.0f * PIF / NN) * (float)t;
        float s, c; sincosf(ang, &s, &c);
        g_G4[i] = pk(g * c, -g * s);
    } else if (idx < 18488) {
        int kk = idx - 18224;
        #pragma unroll
        for (int u = 0; u < 3; u++) {
            int t = kk * (u - 1);
            t %= MM; if (t < 0) t += MM;
            float ang = (2.0f * PIF / MM) * (float)t;
            float s, c; sincosf(ang, &s, &c);
            g_E1[kk * 3 + u] = make_float2(c, -s);
        }
        float ang = (2.0f * PIF / MM) * (float)kk;
        float s, c; sincosf(ang, &s, &c);
        g_U1[kk] = make_float2(1.f + c, -s);
    }
}

__global__ void k_buildWB(const float* __restrict__ w) {
    int kk = blockIdx.x * blockDim.x + threadIdx.x;
    int c = blockIdx.y;
    if (kk >= MM) return;
    float2 e0 = g_E1[kk * 3 + 0], e1 = g_E1[kk * 3 + 1], e2 = g_E1[kk * 3 + 2];
    #pragma unroll
    for (int u = 0; u < 3; u++) {
        float w0 = w[c * 9 + u * 3 + 0];
        float w1 = w[c * 9 + u * 3 + 1];
        float w2 = w[c * 9 + u * 3 + 2];
        g_WB[(c * MM + kk) * 3 + u] =
            make_float2(w0 * e0.x + w1 * e1.x + w2 * e2.x,
                        w0 * e0.y + w1 * e1.y + w2 * e2.y);
    }
}

__global__ void k_buildR(const float* __restrict__ bias) {
    int k2 = threadIdx.x, k1 = blockIdx.x, c = blockIdx.y;
    float alpha = 1.0f / (1.0f + expf(9.0f - bias[c])) + 1e-5f;
    float Vr = 0.f, Vi = 0.f, W2 = 0.f;
    #pragma unroll
    for (int r1 = 0; r1 < 2; r1++)
    #pragma unroll
    for (int r2 = 0; r2 < 2; r2++) {
        int kk1 = k1 + r1 * NN, kk2 = k2 + r2 * NN;
        float fr = 0.f, fi = 0.f;
        #pragma unroll
        for (int u = 0; u < 3; u++) {
            float2 e = g_E1[kk1 * 3 + u];
            float2 b = g_WB[(c * MM + kk2) * 3 + u];
            fr += e.x * b.x - e.y * b.y;
            fi += e.x * b.y + e.y * b.x;
        }
        float2 u1 = g_U1[kk1], u2 = g_U1[kk2];
        float Ur = u1.x * u2.x - u1.y * u2.y;
        float Ui = u1.x * u2.y + u1.y * u2.x;
        Vr += fr * Ur - fi * Ui;
        Vi += fr * Ui + fi * Ur;
        W2 += fr * fr + fi * fi;
    }
    Vr *= 0.25f; Vi *= 0.25f; W2 *= 0.25f;
    float sc = 1.0f / (W2 + alpha) * (1.0f / (float)NPIX);
    g_R[(c * NN + k1) * NN + k2] = make_float2((1.f - Vr) * sc, (-Vi) * sc);
}

// ---------------- kA: quadrant fold of input ----------------
__global__ void kA(const float* __restrict__ x) {
    int idx = blockIdx.x * blockDim.x + threadIdx.x;
    if (idx >= NIMG * 68 * 34) return;
    int img = idx / (68 * 34);
    int rem = idx - img * 68 * 34;
    int n = rem / 34, jp = rem % 34;
    const float* xb = x + img * 16384;
    float vals[4][2];
    #pragma unroll
    for (int h = 0; h < 2; h++) {
        int jt = 2 * jp + h;
        float pp = 0.f, pm = 0.f, mp = 0.f, mm = 0.f;
        if (n < 67 && jt < 67) {
            int n2 = (NN - n) % NN, j2 = (NN - jt) % NN;
            bool nsel = (n != 0 && n != 66);
            bool jsel = (jt != 0 && jt != 66);
            #define XW(R,C) xb[((((R)+126)&127)<<7) + (((C)+126)&127)]
            float a  = XW(n, jt);
            float b  = nsel ? XW(n2, jt) : 0.f;
            float cc = jsel ? XW(n, j2) : 0.f;
            float d  = (nsel && jsel) ? XW(n2, j2) : 0.f;
            #undef XW
            pp = a + b + cc + d;
            pm = jsel ? (a + b - cc - d) : 0.f;
            mp = nsel ? (a - b + cc - d) : 0.f;
            mm = (nsel && jsel) ? (a - b - cc + d) : 0.f;
        }
        vals[0][h] = pp; vals[1][h] = pm; vals[2][h] = mp; vals[3][h] = mm;
    }
    #pragma unroll
    for (int a = 0; a < 4; a++)
        g_xfP[((img * 4 + a) * 68 + n) * 34 + jp] = pk(vals[a][0], vals[a][1]);
}

// ---------------- kBCDE: fully fused per-image-pair pipeline ----------------
// block (17,34)=578 threads; grid = NIMG/2 = 128 (single wave)
// dyn smem 224128:
//   region0 @0 (76160B):
//     phase B: As[68][18] ulonglong2 (19584) + Bs[4][17][35] ulonglong2 @19584 (38080)
//     phase C: CSs[68][69] ulonglong2 (75072)
//     phase D/E (per 33-col tile): Bd3s|G4s [36992] @0 ; T2s[68][34] ulonglong2 @36992
//   region1 @76160 (147968B): Ps[2][68][68] ulonglong2, then SYDYs (same layout)
__global__ void __launch_bounds__(578) kBCDE() {
    ulonglong2* As  = (ulonglong2*)(s_dyn);
    ulonglong2* Bs  = (ulonglong2*)(s_dyn + 19584);
    ulonglong2* CSs = (ulonglong2*)(s_dyn);
    ulonglong2* Bd3s = (ulonglong2*)(s_dyn);
    u64*        G4s  = (u64*)(s_dyn);
    ulonglong2* T2s  = (ulonglong2*)(s_dyn + 36992);
    ulonglong2* Ps   = (ulonglong2*)(s_dyn + 76160);   // also SYDYs

    int img0 = blockIdx.x * 2;
    int tx = threadIdx.x, ty = threadIdx.y, tid = ty * 17 + tx;
    int h2 = (ty >= 17) ? 1 : 0;
    int tyr = ty - 17 * h2;
    const int IMGSTR = 4 * 68 * 34;

    // ================= phase B: P = CSd-transform over n =================
    {
        u64 acc[2][4][4];   // [img][arr][rowi]
        #pragma unroll
        for (int m = 0; m < 2; m++)
            #pragma unroll
            for (int a = 0; a < 4; a++)
                #pragma unroll
                for (int i = 0; i < 4; i++) acc[m][a][i] = 0ULL;

        int jp = tx + 17 * h2;   // 0..33
        for (int k0 = 0; k0 < 68; k0 += 17) {
            for (int i = tid; i < 68 * 17; i += 578) {
                int r = i / 17, n = i - r * 17;
                As[r * 18 + n] = g_CSd[r * 68 + k0 + n];
            }
            for (int i = tid; i < 4 * 17 * 34; i += 578) {
                int a = i / 578;
                int rem = i - a * 578;
                int n = rem / 34, jpx = rem - n * 34;
                int base = (a * 68 + k0 + n) * 34 + jpx;
                ulonglong2 v;
                v.x = g_xfP[img0 * IMGSTR + base];
                v.y = g_xfP[(img0 + 1) * IMGSTR + base];
                Bs[(a * 17 + n) * 35 + jpx] = v;
            }
            __syncthreads();
            #pragma unroll
            for (int n = 0; n < 17; n++) {
                ulonglong2 cs[4], b[4];
                #pragma unroll
                for (int i = 0; i < 4; i++) cs[i] = As[(tyr + 17 * i) * 18 + n];
                #pragma unroll
                for (int a = 0; a < 4; a++) b[a] = Bs[(a * 17 + n) * 35 + jp];
                #pragma unroll
                for (int i = 0; i < 4; i++) {
                    FMA2(acc[0][0][i], cs[i].x, b[0].x); FMA2(acc[1][0][i], cs[i].x, b[0].y);
                    FMA2(acc[0][1][i], cs[i].x, b[1].x); FMA2(acc[1][1][i], cs[i].x, b[1].y);
                    FMA2(acc[0][2][i], cs[i].y, b[2].x); FMA2(acc[1][2][i], cs[i].y, b[2].y);
                    FMA2(acc[0][3][i], cs[i].y, b[3].x); FMA2(acc[1][3][i], cs[i].y, b[3].y);
                }
            }
            __syncthreads();
        }
        int j0 = 2 * jp;
        #pragma unroll
        for (int m = 0; m < 2; m++)
            #pragma unroll
            for (int i = 0; i < 4; i++) {
                int k = tyr + 17 * i;
                float2 p1 = upk(acc[m][0][i]), p2 = upk(acc[m][1][i]);
                float2 p3 = upk(acc[m][2][i]), p4 = upk(acc[m][3][i]);
                ulonglong2 v0, v1;
                v0.x = pk(p1.x, -p3.x); v0.y = pk(-p4.x, p2.x);
                v1.x = pk(p1.y, -p3.y); v1.y = pk(-p4.y, p2.y);
                Ps[m * 4624 + k * 68 + j0]     = v0;
                Ps[m * 4624 + k * 68 + j0 + 1] = v1;
            }
        __syncthreads();
    }

    // ================= phase C: X over j + R + k2-fold -> SYDY (in place over Ps) =================
    for (int i = tid; i < 68 * 68; i += 578) {
        int jj = i / 68, c = i - jj * 68;
        CSs[jj * 69 + c] = g_CSd[c * 68 + jj];
    }
    __syncthreads();

    {
        int m = h2;                       // image index within pair
        u64 UW[4][4], VZ[4][4];           // [rowi][colj]
        #pragma unroll
        for (int i = 0; i < 4; i++)
            #pragma unroll
            for (int j = 0; j < 4; j++) { UW[i][j] = 0ULL; VZ[i][j] = 0ULL; }

        #pragma unroll 4
        for (int jj = 0; jj < 68; jj++) {
            ulonglong2 a[4], bv[4];
            #pragma unroll
            for (int i = 0; i < 4; i++) a[i] = Ps[m * 4624 + (tyr + 17 * i) * 68 + jj];
            #pragma unroll
            for (int j = 0; j < 4; j++) bv[j] = CSs[jj * 69 + 4 * tx + j];
            #pragma unroll
            for (int i = 0; i < 4; i++)
                #pragma unroll
                for (int j = 0; j < 4; j++) {
                    FMA2(UW[i][j], a[i].x, bv[j].x);
                    FMA2(VZ[i][j], a[i].y, bv[j].y);
                }
        }

        int img = img0 + m;
        int ch = img & 63;
        ulonglong2 outv[4][4];
        #pragma unroll
        for (int i = 0; i < 4; i++) {
            int k1 = tyr + 17 * i;
            #pragma unroll
            for (int j = 0; j < 4; j++) {
                int k2 = 4 * tx + j;
                float2 uw = upk(UW[i][j]), vz = upk(VZ[i][j]);
                float U = uw.x, W = uw.y, V = vz.x, Z = vz.y;
                float Xr = U + V, Xi = W - Z;
                float Xr2 = U - V, Xi2 = W + Z;
                int k2m = (NN - k2) % NN;
                float2 R1 = g_R[ch * NPIX + k1 * NN + k2];
                float2 R2 = g_R[ch * NPIX + k1 * NN + k2m];
                float Yr  = Xr * R1.x - Xi * R1.y;
                float Yi  = Xr * R1.y + Xi * R1.x;
                float Yr2 = Xr2 * R2.x - Xi2 * R2.y;
                float Yi2 = Xr2 * R2.y + Xi2 * R2.x;
                bool dbl = (k2 >= 1 && k2 <= 65);
                float sYr = dbl ? Yr + Yr2 : Yr;
                float sYi = dbl ? Yi + Yi2 : Yi;
                float dYi = dbl ? Yi - Yi2 : 0.f;
                float dYr = dbl ? Yr - Yr2 : 0.f;
                outv[i][j].x = pk(sYr, sYi);
                outv[i][j].y = pk(dYi, dYr);
            }
        }
        __syncthreads();   // all Ps reads complete before overwrite
        #pragma unroll
        for (int i = 0; i < 4; i++) {
            int k1 = tyr + 17 * i;
            #pragma unroll
            for (int j = 0; j < 4; j++)
                Ps[m * 4624 + k1 * 68 + 4 * tx + j] = outv[i][j];   // SYDYs
        }
    }
    // Ps region now holds SYDYs

    // ================= phases D+E per 33-column tile =================
    ulonglong2* SYDYs = Ps;
    for (int tile = 0; tile < 4; tile++) {
        __syncthreads();   // prior-tile E reads of G4s/T2s done; SYDY writes done (1st iter)

        // load Bd3 tile [68][33] (pad col 33 with zero)
        for (int i = tid; i < 68 * 34; i += 578) {
            int jj = i / 34, cc = i - jj * 34;
            ulonglong2 v;
            if (cc < 33) v = g_Bd3[jj * 132 + tile * 33 + cc];
            else { v.x = 0ULL; v.y = 0ULL; }
            Bd3s[jj * 34 + cc] = v;
        }
        __syncthreads();

        // phase D: T2 tile = SYDY (68x68) x Bd3 tile (68x33); both images per thread
        {
            u64 accD[2][2][2];   // [img][rowi][colj]
            #pragma unroll
            for (int m = 0; m < 2; m++)
                #pragma unroll
                for (int i = 0; i < 2; i++)
                    #pragma unroll
                    for (int j = 0; j < 2; j++) accD[m][i][j] = 0ULL;
            #pragma unroll 4
            for (int jj = 0; jj < 68; jj++) {
                ulonglong2 a[2][2], bv[2];
                #pragma unroll
                for (int m = 0; m < 2; m++)
                    #pragma unroll
                    for (int i = 0; i < 2; i++)
                        a[m][i] = SYDYs[m * 4624 + (ty + 34 * i) * 68 + jj];
                #pragma unroll
                for (int j = 0; j < 2; j++) bv[j] = Bd3s[jj * 34 + tx * 2 + j];
                #pragma unroll
                for (int m = 0; m < 2; m++)
                    #pragma unroll
                    for (int i = 0; i < 2; i++)
                        #pragma unroll
                        for (int j = 0; j < 2; j++) {
                            FMA2(accD[m][i][j], a[m][i].x, bv[j].x);
                            FMA2(accD[m][i][j], a[m][i].y, bv[j].y);
                        }
            }
            #pragma unroll
            for (int i = 0; i < 2; i++)
                #pragma unroll
                for (int j = 0; j < 2; j++)
                    T2s[(ty + 34 * i) * 34 + tx * 2 + j] =
                        make_ulonglong2(accD[0][i][j], accD[1][i][j]);
        }
        __syncthreads();

        // load G4 (overwrite Bd3s region)
        for (int i = tid; i < 68 * 68; i += 578) G4s[i] = g_G4[i];
        __syncthreads();

        // phase E: z tile = G4 (68x68 over k1) x T2 tile + mirror combine
        {
            u64 accE[2][2][2];   // [img][rowi][colj]
            #pragma unroll
            for (int m = 0; m < 2; m++)
                #pragma unroll
                for (int i = 0; i < 2; i++)
                    #pragma unroll
                    for (int j = 0; j < 2; j++) accE[m][i][j] = 0ULL;
            #pragma unroll 4
            for (int jj = 0; jj < 68; jj++) {
                u64 a[2];
                ulonglong2 b[2];
                #pragma unroll
                for (int i = 0; i < 2; i++) a[i] = G4s[(ty + 34 * i) * 68 + jj];
                #pragma unroll
                for (int j = 0; j < 2; j++) b[j] = T2s[jj * 34 + tx * 2 + j];
                #pragma unroll
                for (int i = 0; i < 2; i++)
                    #pragma unroll
                    for (int j = 0; j < 2; j++) {
                        FMA2(accE[0][i][j], a[i], b[j].x);
                        FMA2(accE[1][i][j], a[i], b[j].y);
                    }
            }
            #pragma unroll
            for (int m = 0; m < 2; m++) {
                float* zb = g_z + (img0 + m) * NPIX;
                #pragma unroll
                for (int i = 0; i < 2; i++) {
                    int m1 = ty + 34 * i;
                    if (m1 > 66) continue;
                    #pragma unroll
                    for (int j = 0; j < 2; j++) {
                        int cx = tx * 2 + j;
                        if (cx >= 33) continue;
                        int col = tile * 33 + cx;
                        float2 v = upk(accE[m][i][j]);
                        zb[m1 * NN + col] = v.x + v.y;
                        if (m1 >= 1 && m1 <= 65)
                            zb[(NN - m1) * NN + col] = v.x - v.y;
                    }
                }
            }
        }
    }
}

// ---------------- final: 2x2 quad per thread, shared m1/m2, exact GELU ----------------
__global__ void k_final(const float* __restrict__ x, const float* __restrict__ wt,
                        float* __restrict__ out) {
    int i = blockIdx.x * blockDim.x + threadIdx.x;   // 256*128*128
    int Q = i & 127, P = (i >> 7) & 127, img = i >> 14;
    int c = img & 63;
    __shared__ float sw[9];
    if (threadIdx.x < 9) sw[threadIdx.x] = wt[c * 9 + threadIdx.x];
    __syncthreads();
    int m1 = P + 2, m2 = Q + 2;
    const float* z = g_z + img * NPIX;
    float z00 = z[m1 * NN + m2],       z01 = z[m1 * NN + m2 + 1];
    float z10 = z[(m1 + 1) * NN + m2], z11 = z[(m1 + 1) * NN + m2 + 1];
    float xv = x[(img * 128 + ((m1 + 126) & 127)) * 128 + ((m2 + 126) & 127)];
    float v00 = xv + sw[4] * z00;
    float v01 = xv + sw[3] * z00 + sw[5] * z01;
    float v10 = xv + sw[1] * z00 + sw[7] * z10;
    float v11 = xv + sw[0] * z00 + sw[2] * z01 + sw[6] * z10 + sw[8] * z11;
    #define GELU(v) (0.5f * (v) * (1.0f + erff((v) * 0.70710678118654752f)))
    float* ob = out + img * 65536;
    *(float2*)&ob[(2 * P) * 256 + 2 * Q]     = make_float2(GELU(v00), GELU(v01));
    *(float2*)&ob[(2 * P + 1) * 256 + 2 * Q] = make_float2(GELU(v10), GELU(v11));
    #undef GELU
}

// ---------------- launch ----------------
extern "C" void kernel_launch(void* const* d_in, const int* in_sizes, int n_in,
                              void* d_out, int out_size) {
    const float* x    = (const float*)d_in[0];   // (4,64,128,128)
    const float* w    = (const float*)d_in[1];   // (1,64,3,3)
    const float* bias = (const float*)d_in[2];   // (1,64,1,1)
    float* out = (float*)d_out;                  // (4,64,256,256)

    static bool attr_done = false;
    if (!attr_done) {
        cudaFuncSetAttribute(kBCDE, cudaFuncAttributeMaxDynamicSharedMemorySize, 224128);
        attr_done = true;
    }

    k_tables<<<(18488 + 255) / 256, 256>>>();
    k_buildWB<<<dim3((MM + 127) / 128, NCH), 128>>>(w);
    k_buildR<<<dim3(67, NCH), NN>>>(bias);

    kA<<<(NIMG * 68 * 34 + 255) / 256, 256>>>(x);

    kBCDE<<<NIMG / 2, dim3(17, 34), 224128>>>();

    k_final<<<(NIMG * 128 * 128) / 256, 256>>>(x, w, out);
}